// round 4
// baseline (speedup 1.0000x reference)
#include <cuda_runtime.h>
#include <cstdint>
#include <cstddef>

#define R_  8
#define K_  32
#define B_  1024
#define D_  256
#define L_  16
#define RK_ (R_ * K_)
#define BT_ 128

// Scratch: per-(r,k,b) assignment loss. 256*1024 floats = 1 MB.
__device__ float g_loss[RK_ * B_];

// ---------------- packed f32x2 helpers (Blackwell FFMA2 path) ----------------

__device__ __forceinline__ unsigned long long pack2(float lo, float hi) {
    unsigned long long r;
    asm("mov.b64 %0, {%1, %2};" : "=l"(r)
        : "r"(__float_as_uint(lo)), "r"(__float_as_uint(hi)));
    return r;
}
__device__ __forceinline__ void unpack2(unsigned long long p, float& lo, float& hi) {
    unsigned int a, b;
    asm("mov.b64 {%0, %1}, %2;" : "=r"(a), "=r"(b) : "l"(p));
    lo = __uint_as_float(a);
    hi = __uint_as_float(b);
}
__device__ __forceinline__ unsigned long long ffma2(unsigned long long a,
                                                    unsigned long long b,
                                                    unsigned long long c) {
    unsigned long long d;
    asm("fma.rn.f32x2 %0, %1, %2, %3;" : "=l"(d) : "l"(a), "l"(b), "l"(c));
    return d;
}

// ---------------------------------------------------------------------------
// Kernel 1: fused x_ = z @ Us^T  and  loss[b] = 0.5 * sum_d (x[b,d]-x_[b,d])^2
// grid = (B/BT, RK), block = 256 threads, thread t owns output column d = t.
// ---------------------------------------------------------------------------
__global__ __launch_bounds__(256) void ksub_gemm_loss(
    const float* __restrict__ x,      // (B, D)
    const float* __restrict__ z,      // (R, K, B, L)
    const float* __restrict__ Us,     // (R, K, D, L)
    float* __restrict__ x_out)        // (R, K, B, D)
{
    const int tid = threadIdx.x;      // d column
    const int rk  = blockIdx.y;
    const int b0  = blockIdx.x * BT_;

    // z tile transposed: zt[l][b_local]; stride 132 keeps 16B alignment for
    // LDS.128 (132*4 = 528 = 33*16) with acceptable store-side conflicts.
    __shared__ __align__(16) float zt[L_][132];
    // Squared diffs for a 16-b chunk: sq[d][b_local]; pad 17 -> conflict-free
    // stores (stride 17 coprime with 32) and conflict-free stage-1 reads.
    __shared__ float sq[256][17];
    __shared__ float red[16][17];

    // Us row for this d, each value duplicated into a packed f32x2 pair.
    unsigned long long ud[L_];
    {
        const float4* up =
            reinterpret_cast<const float4*>(Us + ((size_t)rk * D_ + tid) * L_);
        float4 u0 = up[0], u1 = up[1], u2 = up[2], u3 = up[3];
        ud[0]  = pack2(u0.x, u0.x); ud[1]  = pack2(u0.y, u0.y);
        ud[2]  = pack2(u0.z, u0.z); ud[3]  = pack2(u0.w, u0.w);
        ud[4]  = pack2(u1.x, u1.x); ud[5]  = pack2(u1.y, u1.y);
        ud[6]  = pack2(u1.z, u1.z); ud[7]  = pack2(u1.w, u1.w);
        ud[8]  = pack2(u2.x, u2.x); ud[9]  = pack2(u2.y, u2.y);
        ud[10] = pack2(u2.z, u2.z); ud[11] = pack2(u2.w, u2.w);
        ud[12] = pack2(u3.x, u3.x); ud[13] = pack2(u3.y, u3.y);
        ud[14] = pack2(u3.z, u3.z); ud[15] = pack2(u3.w, u3.w);
    }

    // Load the 128x16 z tile (8 KB, contiguous) and transpose into smem.
    {
        const float4* zp =
            reinterpret_cast<const float4*>(z + ((size_t)rk * B_ + b0) * L_);
        const float4 a  = zp[tid * 2];
        const float4 c4 = zp[tid * 2 + 1];
        const int i  = tid >> 1;
        const int lb = (tid & 1) * 8;
        zt[lb + 0][i] = a.x;  zt[lb + 1][i] = a.y;
        zt[lb + 2][i] = a.z;  zt[lb + 3][i] = a.w;
        zt[lb + 4][i] = c4.x; zt[lb + 5][i] = c4.y;
        zt[lb + 6][i] = c4.z; zt[lb + 7][i] = c4.w;
    }
    __syncthreads();

    const float* xcol = x + tid;
    float* ocol = x_out + ((size_t)rk * B_ + b0) * D_ + tid;

    #pragma unroll 1
    for (int c = 0; c < BT_; c += 16) {
        #pragma unroll
        for (int j = 0; j < 16; j += 4) {
            const int b = c + j;
            unsigned long long acc0 = 0ull, acc1 = 0ull;  // {0.f, 0.f}
            #pragma unroll
            for (int l = 0; l < L_; l++) {
                // uniform broadcast LDS.128: z for 4 consecutive b's
                const ulonglong2 zq =
                    *reinterpret_cast<const ulonglong2*>(&zt[l][b]);
                acc0 = ffma2(zq.x, ud[l], acc0);   // b, b+1
                acc1 = ffma2(zq.y, ud[l], acc1);   // b+2, b+3
            }
            float v0, v1, v2, v3;
            unpack2(acc0, v0, v1);
            unpack2(acc1, v2, v3);

            // coalesced x_ stores (warp = 128B row segment)
            ocol[(size_t)(b + 0) * D_] = v0;
            ocol[(size_t)(b + 1) * D_] = v1;
            ocol[(size_t)(b + 2) * D_] = v2;
            ocol[(size_t)(b + 3) * D_] = v3;

            const float x0 = __ldg(xcol + (size_t)(b0 + b + 0) * D_);
            const float x1 = __ldg(xcol + (size_t)(b0 + b + 1) * D_);
            const float x2 = __ldg(xcol + (size_t)(b0 + b + 2) * D_);
            const float x3 = __ldg(xcol + (size_t)(b0 + b + 3) * D_);

            const float d0 = x0 - v0, d1 = x1 - v1;
            const float d2 = x2 - v2, d3 = x3 - v3;
            sq[tid][j + 0] = d0 * d0;
            sq[tid][j + 1] = d1 * d1;
            sq[tid][j + 2] = d2 * d2;
            sq[tid][j + 3] = d3 * d3;
        }
        __syncthreads();

        // Stage 1: thread (seg, bsel) sums 16 d's of column bsel.
        {
            const int bsel = tid & 15;
            const int seg  = tid >> 4;
            float s = 0.f;
            #pragma unroll
            for (int i2 = 0; i2 < 16; i2++) s += sq[seg * 16 + i2][bsel];
            red[seg][bsel] = s;
        }
        __syncthreads();

        // Stage 2: 16 threads finish the 16-way segment sum and store loss.
        // Reference loss = 0.5 * sum_d (x - x_)^2  -> apply the 0.5 HERE.
        if (tid < 16) {
            float s = 0.f;
            #pragma unroll
            for (int i2 = 0; i2 < 16; i2++) s += red[i2][tid];
            g_loss[rk * B_ + b0 + c + tid] = 0.5f * s;
        }
        __syncthreads();
    }
}

// ---------------------------------------------------------------------------
// Kernel 2: per (b, r) top-2 (min) over K, one-hot c, EMA stats, obj.
// grid = R blocks, block = B threads (thread = b).
// ---------------------------------------------------------------------------
__global__ __launch_bounds__(1024) void ksub_assign(
    const float* __restrict__ c_mean_in,   // (R, K)
    const float* __restrict__ value_in,    // (R, K)
    float* __restrict__ c_out,             // (B, R, K)
    float* __restrict__ obj_out,           // (R,)
    float* __restrict__ new_c_mean,        // (R, K)
    float* __restrict__ new_value)         // (R, K)
{
    const int r = blockIdx.x;
    const int b = threadIdx.x;

    __shared__ float cnt[K_];
    __shared__ float vsum[K_];
    __shared__ float osum;
    if (b < K_) { cnt[b] = 0.f; vsum[b] = 0.f; }
    if (b == 0) osum = 0.f;
    __syncthreads();

    float m1 = 3.402823466e38f, m2 = 3.402823466e38f;
    int g = 0;
    #pragma unroll
    for (int k = 0; k < K_; k++) {
        const float l = g_loss[(r * K_ + k) * B_ + b];  // coalesced per k
        if (l < m1) { m2 = m1; m1 = l; g = k; }         // strict < : top_k ties -> lowest idx
        else if (l < m2) { m2 = l; }
    }

    // one-hot row c[b, r, :]
    float* crow = c_out + ((size_t)b * R_ + r) * K_;
    const float4 z4 = make_float4(0.f, 0.f, 0.f, 0.f);
    #pragma unroll
    for (int q = 0; q < K_ / 4; q++)
        reinterpret_cast<float4*>(crow)[q] = z4;
    crow[g] = 1.0f;

    atomicAdd(&cnt[g], 1.0f);
    atomicAdd(&vsum[g], m2 - m1);
    atomicAdd(&osum, m1);
    __syncthreads();

    const float invB = 1.0f / (float)B_;
    if (b < K_) {
        new_c_mean[r * K_ + b] = 0.9f * c_mean_in[r * K_ + b] + 0.1f * (cnt[b]  * invB);
        new_value [r * K_ + b] = 0.9f * value_in [r * K_ + b] + 0.1f * (vsum[b] * invB);
    }
    if (b == 0) obj_out[r] = osum * invB;
}

// Kernel 3: obj_mean = mean(obj)
__global__ void ksub_objmean(const float* __restrict__ obj, float* __restrict__ obj_mean) {
    if (threadIdx.x == 0) {
        float s = 0.f;
        #pragma unroll
        for (int r = 0; r < R_; r++) s += obj[r];
        *obj_mean = s * (1.0f / (float)R_);
    }
}

// ---------------------------------------------------------------------------
extern "C" void kernel_launch(void* const* d_in, const int* in_sizes, int n_in,
                              void* d_out, int out_size)
{
    (void)in_sizes; (void)n_in; (void)out_size;
    const float* x   = (const float*)d_in[0];   // (B, D)
    const float* z   = (const float*)d_in[1];   // (R, K, B, L)
    const float* Us  = (const float*)d_in[2];   // (R, K, D, L)
    const float* cm  = (const float*)d_in[3];   // (R, K)
    const float* val = (const float*)d_in[4];   // (R, K)

    float* out      = (float*)d_out;
    float* x_out    = out;                                   // 67108864
    float* c_out    = x_out + (size_t)RK_ * B_ * D_;         //   262144
    float* obj_out  = c_out + (size_t)B_ * R_ * K_;          //        8
    float* obj_mean = obj_out + R_;                          //        1
    float* ncm      = obj_mean + 1;                          //      256
    float* nval     = ncm + RK_;                             //      256

    dim3 g1(B_ / BT_, RK_);
    ksub_gemm_loss<<<g1, 256>>>(x, z, Us, x_out);
    ksub_assign<<<R_, B_>>>(cm, val, c_out, obj_out, ncm, nval);
    ksub_objmean<<<1, 32>>>(obj_out, obj_mean);
}

// round 5
// speedup vs baseline: 1.3973x; 1.3973x over previous
#include <cuda_runtime.h>
#include <cstdint>
#include <cstddef>

#define R_  8
#define K_  32
#define B_  1024
#define D_  256
#define L_  16
#define RK_ (R_ * K_)
#define BT_ 128

// Scratch: per-(r,k,b) assignment loss (1 MB) + stat partials.
__device__ float g_loss[RK_ * B_];
__device__ float g_cnt[RK_];
__device__ float g_vsum[RK_];
__device__ float g_osum[R_];

// ---------------- packed f32x2 helpers (Blackwell FFMA2 path) ----------------

__device__ __forceinline__ unsigned long long pack2(float lo, float hi) {
    unsigned long long r;
    asm("mov.b64 %0, {%1, %2};" : "=l"(r)
        : "r"(__float_as_uint(lo)), "r"(__float_as_uint(hi)));
    return r;
}
__device__ __forceinline__ void unpack2(unsigned long long p, float& lo, float& hi) {
    unsigned int a, b;
    asm("mov.b64 {%0, %1}, %2;" : "=r"(a), "=r"(b) : "l"(p));
    lo = __uint_as_float(a);
    hi = __uint_as_float(b);
}
__device__ __forceinline__ unsigned long long ffma2(unsigned long long a,
                                                    unsigned long long b,
                                                    unsigned long long c) {
    unsigned long long d;
    asm("fma.rn.f32x2 %0, %1, %2, %3;" : "=l"(d) : "l"(a), "l"(b), "l"(c));
    return d;
}
__device__ __forceinline__ unsigned long long fadd2(unsigned long long a,
                                                    unsigned long long b) {
    unsigned long long d;
    asm("add.rn.f32x2 %0, %1, %2;" : "=l"(d) : "l"(a), "l"(b));
    return d;
}

// ---------------------------------------------------------------------------
// Kernel 1: fused x_ = z @ Us^T and loss[b] = 0.5 * sum_d (x[b,d]-x_[b,d])^2
// grid = (B/BT, RK), block = 256 threads.
// Thread t owns d-quad dq = (t & 63) (d = 4*dq..4*dq+3) and b-group (t >> 6):
// 32 of the 128 tile b's. Us quad lives in registers as f32x2 pairs; z[b][:]
// is a uniform 4x LDS.128 broadcast reused across all 4 d's.
// ---------------------------------------------------------------------------
__global__ __launch_bounds__(256, 2) void ksub_gemm_loss(
    const float* __restrict__ x,      // (B, D)
    const float* __restrict__ z,      // (R, K, B, L)
    const float* __restrict__ Us,     // (R, K, D, L)
    float* __restrict__ x_out)        // (R, K, B, D)
{
    const int tid = threadIdx.x;
    const int dq  = tid & 63;         // d-quad index, d = 4*dq
    const int bg  = tid >> 6;         // 0..3 b-group
    const int rk  = blockIdx.y;
    const int b0  = blockIdx.x * BT_;

    // z tile, natural layout: zs[b][l], 128*16 floats = 8 KB.
    __shared__ __align__(16) float4 zs4[BT_ * 4];
    // per-(b, dq) loss partials; pad 68 -> row 272B (16B-aligned, conflict-ok)
    __shared__ __align__(16) float arr[BT_][68];

    // ---- Load Us quad and pack into f32x2 pairs: p01 = (d0,d1), p23 = (d2,d3)
    unsigned long long p01[L_], p23[L_];
    {
        const float4* u4 =
            reinterpret_cast<const float4*>(Us + ((size_t)rk * D_ + dq * 4) * L_);
        float4 A0 = u4[0],  A1 = u4[1],  A2 = u4[2],  A3 = u4[3];    // row d0
        float4 B0 = u4[4],  B1 = u4[5],  B2 = u4[6],  B3 = u4[7];    // row d1
        float4 C0 = u4[8],  C1 = u4[9],  C2 = u4[10], C3 = u4[11];   // row d2
        float4 E0 = u4[12], E1 = u4[13], E2 = u4[14], E3 = u4[15];   // row d3
        p01[0]  = pack2(A0.x, B0.x); p01[1]  = pack2(A0.y, B0.y);
        p01[2]  = pack2(A0.z, B0.z); p01[3]  = pack2(A0.w, B0.w);
        p01[4]  = pack2(A1.x, B1.x); p01[5]  = pack2(A1.y, B1.y);
        p01[6]  = pack2(A1.z, B1.z); p01[7]  = pack2(A1.w, B1.w);
        p01[8]  = pack2(A2.x, B2.x); p01[9]  = pack2(A2.y, B2.y);
        p01[10] = pack2(A2.z, B2.z); p01[11] = pack2(A2.w, B2.w);
        p01[12] = pack2(A3.x, B3.x); p01[13] = pack2(A3.y, B3.y);
        p01[14] = pack2(A3.z, B3.z); p01[15] = pack2(A3.w, B3.w);
        p23[0]  = pack2(C0.x, E0.x); p23[1]  = pack2(C0.y, E0.y);
        p23[2]  = pack2(C0.z, E0.z); p23[3]  = pack2(C0.w, E0.w);
        p23[4]  = pack2(C1.x, E1.x); p23[5]  = pack2(C1.y, E1.y);
        p23[6]  = pack2(C1.z, E1.z); p23[7]  = pack2(C1.w, E1.w);
        p23[8]  = pack2(C2.x, E2.x); p23[9]  = pack2(C2.y, E2.y);
        p23[10] = pack2(C2.z, E2.z); p23[11] = pack2(C2.w, E2.w);
        p23[12] = pack2(C3.x, E3.x); p23[13] = pack2(C3.y, E3.y);
        p23[14] = pack2(C3.z, E3.z); p23[15] = pack2(C3.w, E3.w);
    }

    // ---- Stage z tile (contiguous copy, no transpose)
    {
        const float4* zg =
            reinterpret_cast<const float4*>(z + ((size_t)rk * B_ + b0) * L_);
        zs4[tid]       = zg[tid];
        zs4[tid + 256] = zg[tid + 256];
    }
    __syncthreads();

    const float4* x4 =
        reinterpret_cast<const float4*>(x) + (size_t)b0 * (D_ / 4) + dq;
    float4* o4 =
        reinterpret_cast<float4*>(x_out) +
        ((size_t)rk * B_ + b0) * (D_ / 4) + dq;

    const int blo = bg * 32;
    #pragma unroll 2
    for (int b = blo; b < blo + 32; ++b) {
        // 4 independent FFMA2 chains (dep gap 8 >= lat 4)
        unsigned long long a01a = 0ull, a01b = 0ull;
        unsigned long long a23a = 0ull, a23b = 0ull;
        #pragma unroll
        for (int l4 = 0; l4 < 4; ++l4) {
            const float4 zq = zs4[b * 4 + l4];          // uniform broadcast
            const unsigned long long z0 = pack2(zq.x, zq.x);
            const unsigned long long z1 = pack2(zq.y, zq.y);
            const unsigned long long z2 = pack2(zq.z, zq.z);
            const unsigned long long z3 = pack2(zq.w, zq.w);
            a01a = ffma2(z0, p01[l4 * 4 + 0], a01a);
            a23a = ffma2(z0, p23[l4 * 4 + 0], a23a);
            a01b = ffma2(z1, p01[l4 * 4 + 1], a01b);
            a23b = ffma2(z1, p23[l4 * 4 + 1], a23b);
            a01a = ffma2(z2, p01[l4 * 4 + 2], a01a);
            a23a = ffma2(z2, p23[l4 * 4 + 2], a23a);
            a01b = ffma2(z3, p01[l4 * 4 + 3], a01b);
            a23b = ffma2(z3, p23[l4 * 4 + 3], a23b);
        }
        const unsigned long long acc01 = fadd2(a01a, a01b);
        const unsigned long long acc23 = fadd2(a23a, a23b);

        float v0, v1, v2, v3;
        unpack2(acc01, v0, v1);
        unpack2(acc23, v2, v3);

        o4[(size_t)b * (D_ / 4)] = make_float4(v0, v1, v2, v3);  // coalesced 512B

        const float4 xv = __ldg(x4 + (size_t)b * (D_ / 4));
        const float d0 = xv.x - v0, d1 = xv.y - v1;
        const float d2 = xv.z - v2, d3 = xv.w - v3;
        arr[b][dq] = fmaf(d3, d3, fmaf(d2, d2, fmaf(d1, d1, d0 * d0)));
    }
    __syncthreads();

    // ---- Deferred loss reduction: thread t < 128 sums arr[t][0..63].
    if (tid < BT_) {
        const float4* row = reinterpret_cast<const float4*>(arr[tid]);
        float4 s0 = row[0];
        #pragma unroll
        for (int j = 1; j < 16; ++j) {
            const float4 v = row[j];
            s0.x += v.x; s0.y += v.y; s0.z += v.z; s0.w += v.w;
        }
        g_loss[rk * B_ + b0 + tid] = 0.5f * ((s0.x + s0.y) + (s0.z + s0.w));
    }
}

// ---------------------------------------------------------------------------
// Kernel 0: zero stat partials (runs before kernel 2's atomics each replay)
// ---------------------------------------------------------------------------
__global__ void ksub_init() {
    const int t = threadIdx.x;
    if (t < RK_) { g_cnt[t] = 0.f; g_vsum[t] = 0.f; }
    if (t < R_)  g_osum[t] = 0.f;
}

// ---------------------------------------------------------------------------
// Kernel 2: per (b, r) top-2 (min) over K, one-hot c, partial stats.
// grid = 64 blocks: r = bx >> 3, b-tile = bx & 7. 128 threads, thread = b.
// ---------------------------------------------------------------------------
__global__ __launch_bounds__(128) void ksub_assign(
    float* __restrict__ c_out)             // (B, R, K)
{
    const int r = blockIdx.x >> 3;
    const int b = (blockIdx.x & 7) * 128 + threadIdx.x;
    const int t = threadIdx.x;

    __shared__ float cnt[K_];
    __shared__ float vsum[K_];
    __shared__ float osum;
    if (t < K_) { cnt[t] = 0.f; vsum[t] = 0.f; }
    if (t == 0) osum = 0.f;
    __syncthreads();

    float m1 = 3.402823466e38f, m2 = 3.402823466e38f;
    int g = 0;
    #pragma unroll
    for (int k = 0; k < K_; k++) {
        const float l = g_loss[(r * K_ + k) * B_ + b];  // coalesced per k
        if (l < m1) { m2 = m1; m1 = l; g = k; }         // strict <: ties -> lowest idx
        else if (l < m2) { m2 = l; }
    }

    // one-hot row c[b, r, :]
    float* crow = c_out + ((size_t)b * R_ + r) * K_;
    const float4 z4 = make_float4(0.f, 0.f, 0.f, 0.f);
    #pragma unroll
    for (int q = 0; q < K_ / 4; q++)
        reinterpret_cast<float4*>(crow)[q] = z4;
    crow[g] = 1.0f;

    atomicAdd(&cnt[g], 1.0f);
    atomicAdd(&vsum[g], m2 - m1);
    atomicAdd(&osum, m1);
    __syncthreads();

    if (t < K_) {
        atomicAdd(&g_cnt[r * K_ + t], cnt[t]);
        atomicAdd(&g_vsum[r * K_ + t], vsum[t]);
    }
    if (t == 0) atomicAdd(&g_osum[r], osum);
}

// ---------------------------------------------------------------------------
// Kernel 3: finalize EMAs, obj, obj_mean
// ---------------------------------------------------------------------------
__global__ void ksub_finalize(
    const float* __restrict__ c_mean_in,   // (R, K)
    const float* __restrict__ value_in,    // (R, K)
    float* __restrict__ obj_out,           // (R,)
    float* __restrict__ obj_mean,          // (1,)
    float* __restrict__ new_c_mean,        // (R, K)
    float* __restrict__ new_value)         // (R, K)
{
    const int t = threadIdx.x;
    const float invB = 1.0f / (float)B_;
    if (t < RK_) {
        new_c_mean[t] = 0.9f * c_mean_in[t] + 0.1f * (g_cnt[t]  * invB);
        new_value [t] = 0.9f * value_in [t] + 0.1f * (g_vsum[t] * invB);
    }
    if (t < R_) obj_out[t] = g_osum[t] * invB;
    if (t == 0) {
        float s = 0.f;
        #pragma unroll
        for (int r = 0; r < R_; r++) s += g_osum[r] * invB;
        *obj_mean = s * (1.0f / (float)R_);
    }
}

// ---------------------------------------------------------------------------
extern "C" void kernel_launch(void* const* d_in, const int* in_sizes, int n_in,
                              void* d_out, int out_size)
{
    (void)in_sizes; (void)n_in; (void)out_size;
    const float* x   = (const float*)d_in[0];   // (B, D)
    const float* z   = (const float*)d_in[1];   // (R, K, B, L)
    const float* Us  = (const float*)d_in[2];   // (R, K, D, L)
    const float* cm  = (const float*)d_in[3];   // (R, K)
    const float* val = (const float*)d_in[4];   // (R, K)

    float* out      = (float*)d_out;
    float* x_out    = out;                                   // 67108864
    float* c_out    = x_out + (size_t)RK_ * B_ * D_;         //   262144
    float* obj_out  = c_out + (size_t)B_ * R_ * K_;          //        8
    float* obj_mean = obj_out + R_;                          //        1
    float* ncm      = obj_mean + 1;                          //      256
    float* nval     = ncm + RK_;                             //      256

    ksub_init<<<1, 288>>>();
    dim3 g1(B_ / BT_, RK_);
    ksub_gemm_loss<<<g1, 256>>>(x, z, Us, x_out);
    ksub_assign<<<64, 128>>>(c_out);
    ksub_finalize<<<1, 256>>>(cm, val, obj_out, obj_mean, ncm, nval);
}